// round 1
// baseline (speedup 1.0000x reference)
#include <cuda_runtime.h>
#include <math.h>

#define B_    32
#define N_    512
#define F_    64
#define H_    8
#define HID_  64
#define OUT_  64

// ---------------- scratch (device globals; no allocation) ----------------
__device__ float g_Wh  [B_*H_*N_*HID_];   // 33.5 MB  layer1 per-head features
__device__ float g_ssrc[B_*H_*N_];
__device__ float g_sdst[B_*H_*N_];
__device__ float g_x   [B_*N_*H_*HID_];   // 33.5 MB  transposed post-attn layer1
__device__ float g_Wh2 [B_*N_*OUT_];      // 4 MB
__device__ float g_s2s [B_*N_];
__device__ float g_s2d [B_*N_];
__device__ float g_z   [B_*N_*OUT_];      // 4 MB (layer2 attn out, = fc1 input)
__device__ float g_p1  [16*B_*256];       // fc1 split-K partials
__device__ float g_z1  [B_*256];
__device__ float g_z2  [B_*256];

// ---------------- K1: Wh[b,h] = feat[b] @ W_heads[h]  (512x64 @ 64x64) ----
__global__ void k_wh(const float* __restrict__ state, const float* __restrict__ Wheads) {
    int bt = blockIdx.x;
    int rt = bt & 7, h = (bt >> 3) & 7, b = bt >> 6;
    __shared__ float As[64*65];
    __shared__ float Ws[64*64];
    int tid = threadIdx.x;
    const float* ap = state + b*(N_*F_) + rt*64*F_;
    #pragma unroll
    for (int i = 0; i < 16; i++) {
        int idx = tid + i*256;
        As[(idx >> 6)*65 + (idx & 63)] = ap[idx];
    }
    const float* wp = Wheads + h*F_*HID_;
    #pragma unroll
    for (int i = 0; i < 16; i++) {
        int idx = tid + i*256;
        Ws[idx] = wp[idx];
    }
    __syncthreads();
    int ty = tid >> 4, tx = tid & 15;
    float acc[4][4] = {};
    const float4* Ws4 = (const float4*)Ws;
    #pragma unroll 4
    for (int k = 0; k < 64; k++) {
        float4 wv = Ws4[k*16 + tx];
        #pragma unroll
        for (int i = 0; i < 4; i++) {
            float a = As[(ty*4+i)*65 + k];
            acc[i][0] += a*wv.x; acc[i][1] += a*wv.y;
            acc[i][2] += a*wv.z; acc[i][3] += a*wv.w;
        }
    }
    float* op = g_Wh + ((size_t)(b*H_ + h)*N_ + rt*64)*HID_;
    #pragma unroll
    for (int i = 0; i < 4; i++) {
        float4 v = make_float4(acc[i][0], acc[i][1], acc[i][2], acc[i][3]);
        ((float4*)(op + (ty*4+i)*64))[tx] = v;
    }
}

// ---------------- K1b/K3b: attention scores s = Wh @ a ----
__global__ void k_scores(const float* __restrict__ asrc, const float* __restrict__ adst,
                         int layer, int heads) {
    const float* Wh  = layer ? g_Wh2  : g_Wh;
    float* ssrc      = layer ? g_s2s  : g_ssrc;
    float* sdst      = layer ? g_s2d  : g_sdst;
    int bh = blockIdx.x;
    int hoff = (bh % heads)*64;
    const float* base = Wh + (size_t)bh*N_*64;
    int tid = threadIdx.x, w = tid >> 5, l = tid & 31;
    float a0s = asrc[hoff + l],      a1s = asrc[hoff + 32 + l];
    float a0d = adst[hoff + l],      a1d = adst[hoff + 32 + l];
    for (int r = w; r < N_; r += 16) {
        float v0 = base[r*64 + l], v1 = base[r*64 + 32 + l];
        float ss = v0*a0s + v1*a1s;
        float sd = v0*a0d + v1*a1d;
        #pragma unroll
        for (int o = 16; o; o >>= 1) {
            ss += __shfl_xor_sync(0xffffffffu, ss, o);
            sd += __shfl_xor_sync(0xffffffffu, sd, o);
        }
        if (l == 0) { ssrc[bh*N_ + r] = ss; sdst[bh*N_ + r] = sd; }
    }
}

// ---------------- K2/K4: sorted-prefix GAT attention ----
// p_ij factorizes around the leaky_relu kink; sort d descending -> prefix lookup.
__global__ void k_attend(int layer, int heads, int rowStride, int applyElu) {
    extern __shared__ float sm[];
    float* ds   = sm;                    // 512
    int*   ji   = (int*)(sm + 512);      // 512
    float* Ed   = sm + 1024;             // 512
    float* Ed2  = sm + 1536;             // 512
    float* WhS  = sm + 2048;             // 512*64
    float* CP1  = WhS  + 512*64;         // 17*64
    float* CP2  = CP1  + 17*64;          // 17*64
    float* CPd1 = CP2  + 17*64;          // 32
    float* CPd2 = CPd1 + 32;             // 32

    const float* Wh   = layer ? g_Wh2 : g_Wh;
    const float* ssrc = layer ? g_s2s : g_ssrc;
    const float* sdst = layer ? g_s2d : g_sdst;
    float*       out  = layer ? g_z   : g_x;

    int bh = blockIdx.x;
    int hoff = (bh % heads)*64;
    const float* whbase = Wh + (size_t)bh*N_*64;
    int tid = threadIdx.x;

    ds[tid] = sdst[bh*N_ + tid];
    ji[tid] = tid;

    // bitonic sort, descending by d
    for (int k2 = 2; k2 <= 512; k2 <<= 1)
        for (int j = k2 >> 1; j > 0; j >>= 1) {
            __syncthreads();
            int i = tid, x = tid ^ j;
            if (x > i) {
                float a = ds[i], b = ds[x];
                bool desc = ((i & k2) == 0);
                if (desc ? (a < b) : (a > b)) {
                    ds[i] = b; ds[x] = a;
                    int t = ji[i]; ji[i] = ji[x]; ji[x] = t;
                }
            }
        }
    __syncthreads();
    float dmax = ds[0];
    {
        float dv = ds[tid] - dmax;
        Ed [tid] = expf(dv);
        Ed2[tid] = expf(0.2f*dv);
    }
    // gather Wh rows in sorted order (coalesced per warp)
    int w = tid >> 5, l = tid & 31;
    for (int u = w; u < 512; u += 16) {
        int jj = ji[u];
        float2 v = ((const float2*)(whbase + jj*64))[l];
        ((float2*)(WhS + u*64))[l] = v;
    }
    __syncthreads();
    // chunk sums (granularity 32) for both branches
    for (int q = tid; q < 1024; q += 512) {
        int c = q >> 6, o = q & 63;
        float s1 = 0.f, s2 = 0.f;
        int ub = c*32;
        #pragma unroll 4
        for (int u = 0; u < 32; u++) {
            float wv = WhS[(ub + u)*64 + o];
            s1 += Ed [ub + u]*wv;
            s2 += Ed2[ub + u]*wv;
        }
        CP1[(c+1)*64 + o] = s1;
        CP2[(c+1)*64 + o] = s2;
    }
    if (tid < 64) { CP1[tid] = 0.f; CP2[tid] = 0.f; }
    if (tid < 16) {
        int c = tid; float s1 = 0.f, s2 = 0.f;
        for (int u = c*32; u < c*32 + 32; u++) { s1 += Ed[u]; s2 += Ed2[u]; }
        CPd1[c+1] = s1; CPd2[c+1] = s2;
    }
    if (tid == 0) { CPd1[0] = 0.f; CPd2[0] = 0.f; }
    __syncthreads();
    // exclusive-to-inclusive scans over 16 chunks
    if (tid < 64) {
        for (int c = 1; c <= 16; c++) CP1[c*64 + tid] += CP1[(c-1)*64 + tid];
    } else if (tid < 128) {
        int o = tid - 64;
        for (int c = 1; c <= 16; c++) CP2[c*64 + o] += CP2[(c-1)*64 + o];
    } else if (tid == 128) {
        for (int c = 1; c <= 16; c++) { CPd1[c] += CPd1[c-1]; CPd2[c] += CPd2[c-1]; }
    }
    __syncthreads();

    float Td2 = CPd2[16];
    int bb = bh / heads;
    for (int r = w; r < 512; r += 16) {
        float s   = ssrc[bh*N_ + r];
        float sd0 = s + dmax;
        float m   = sd0 > 0.f ? sd0 : 0.2f*sd0;
        float A   = expf(sd0 - m);
        float Bv  = expf(0.2f*sd0 - m);
        float thr = -s;
        int lo = 0, hi = 512;
        #pragma unroll
        for (int it = 0; it < 9; it++) {
            int mid = (lo + hi) >> 1;
            if (ds[mid] > thr) lo = mid + 1; else hi = mid;
        }
        int k = lo;
        int c = k >> 5;
        float a1x = 0.f, a1y = 0.f, a2x = 0.f, a2y = 0.f, pe1 = 0.f, pe2 = 0.f;
        for (int u = c*32; u < k; u++) {
            float e1 = Ed[u], e2 = Ed2[u];
            float2 wv = ((const float2*)(WhS + u*64))[l];
            a1x += e1*wv.x; a1y += e1*wv.y;
            a2x += e2*wv.x; a2y += e2*wv.y;
            pe1 += e1;      pe2 += e2;
        }
        float2 cp1 = ((const float2*)(CP1 + c*64))[l];
        float2 cp2 = ((const float2*)(CP2 + c*64))[l];
        float2 t2  = ((const float2*)(CP2 + 16*64))[l];
        float posx = cp1.x + a1x, posy = cp1.y + a1y;
        float negx = t2.x - cp2.x - a2x, negy = t2.y - cp2.y - a2y;
        float den  = A*(CPd1[c] + pe1) + Bv*(Td2 - CPd2[c] - pe2);
        float inv  = 1.f/den;
        float o0 = (A*posx + Bv*negx)*inv;
        float o1 = (A*posy + Bv*negy)*inv;
        if (applyElu) {
            o0 = o0 > 0.f ? o0 : expm1f(o0);
            o1 = o1 > 0.f ? o1 : expm1f(o1);
        }
        ((float2*)(out + ((size_t)(bb*N_ + r))*rowStride + hoff))[l] = make_float2(o0, o1);
    }
}

// ---------------- K3: Wh2 = x @ W_out  (16384x512 @ 512x64) ----
__global__ void k_gemm2(const float* __restrict__ Wout) {
    int rt = blockIdx.x;
    __shared__ float Xs[64*65];
    __shared__ float Ws[64*64];
    int tid = threadIdx.x;
    int ty = tid >> 4, tx = tid & 15;
    float acc[4][4] = {};
    const float* xp = g_x + (size_t)rt*64*512;
    for (int kc = 0; kc < 8; kc++) {
        __syncthreads();
        #pragma unroll
        for (int i = 0; i < 16; i++) {
            int idx = tid + i*256;
            int r = idx >> 6, kk = idx & 63;
            Xs[r*65 + kk] = xp[r*512 + kc*64 + kk];
        }
        #pragma unroll
        for (int i = 0; i < 16; i++) {
            int idx = tid + i*256;
            Ws[idx] = Wout[kc*64*64 + idx];
        }
        __syncthreads();
        const float4* Ws4 = (const float4*)Ws;
        #pragma unroll 4
        for (int k = 0; k < 64; k++) {
            float4 wv = Ws4[k*16 + tx];
            #pragma unroll
            for (int i = 0; i < 4; i++) {
                float a = Xs[(ty*4+i)*65 + k];
                acc[i][0] += a*wv.x; acc[i][1] += a*wv.y;
                acc[i][2] += a*wv.z; acc[i][3] += a*wv.w;
            }
        }
    }
    float* op = g_Wh2 + (size_t)rt*64*64;
    #pragma unroll
    for (int i = 0; i < 4; i++) {
        float4 v = make_float4(acc[i][0], acc[i][1], acc[i][2], acc[i][3]);
        ((float4*)(op + (ty*4+i)*64))[tx] = v;
    }
}

// ---------------- K5: fc1 split-K partials  z(32,32768) @ w1(32768,256) ----
__global__ void k_fc1(const float* __restrict__ w1) {
    extern __shared__ float sm[];
    float* zs = sm;              // 32*512
    float* ws = sm + 32*512;     // 512*16
    int cg = blockIdx.x, ksp = blockIdx.y;
    int c0 = cg*16;
    int tid = threadIdx.x;
    int c = tid & 15, b0 = tid >> 4;
    float acc1 = 0.f, acc2 = 0.f;
    for (int ch = 0; ch < 4; ch++) {
        int kb = ksp*2048 + ch*512;
        __syncthreads();
        const float4* zg = (const float4*)g_z;
        float4* zs4 = (float4*)zs;
        #pragma unroll
        for (int i = 0; i < 16; i++) {
            int idx = tid + i*256;            // 0..4095 float4
            int b = idx >> 7, k4 = idx & 127;
            zs4[b*128 + k4] = zg[b*8192 + (kb >> 2) + k4];
        }
        const float4* wg = (const float4*)w1;
        float4* ws4 = (float4*)ws;
        #pragma unroll
        for (int i = 0; i < 8; i++) {
            int idx = tid + i*256;            // 0..2047 float4
            int r = idx >> 2, c4 = idx & 3;
            ws4[r*4 + c4] = wg[(size_t)(kb + r)*64 + cg*4 + c4];
        }
        __syncthreads();
        #pragma unroll 4
        for (int k = 0; k < 512; k++) {
            float wv = ws[k*16 + c];
            acc1 += zs[b0*512 + k]*wv;
            acc2 += zs[(b0+16)*512 + k]*wv;
        }
    }
    g_p1[(ksp*32 + b0     )*256 + c0 + c] = acc1;
    g_p1[(ksp*32 + b0 + 16)*256 + c0 + c] = acc2;
}

// ---------------- K6: reduce split-K + bias + relu ----
__global__ void k_fc1red(const float* __restrict__ b1) {
    int b = blockIdx.x, c = threadIdx.x;
    float acc = b1[c];
    #pragma unroll
    for (int ks = 0; ks < 16; ks++) acc += g_p1[(ks*32 + b)*256 + c];
    g_z1[b*256 + c] = fmaxf(acc, 0.f);
}

// ---------------- K7: fc2 + relu ----
__global__ void k_fc2(const float* __restrict__ w2, const float* __restrict__ b2) {
    __shared__ float z1s[256];
    int b = blockIdx.x, c = threadIdx.x;
    z1s[c] = g_z1[b*256 + c];
    __syncthreads();
    float acc = b2[c];
    #pragma unroll 4
    for (int k = 0; k < 256; k++) acc += z1s[k]*w2[k*256 + c];
    g_z2[b*256 + c] = fmaxf(acc, 0.f);
}

// ---------------- K8: fc3 + tanh ----
__global__ void k_fc3(const float* __restrict__ w3, const float* __restrict__ b3,
                      float* __restrict__ out) {
    __shared__ float z2s[256];
    int b = blockIdx.x, tid = threadIdx.x;
    z2s[tid] = g_z2[b*256 + tid];
    z2s[tid + 128] = g_z2[b*256 + tid + 128];
    __syncthreads();
    int c = tid >> 5, l = tid & 31;
    float acc = 0.f;
    #pragma unroll
    for (int k = l; k < 256; k += 32) acc += z2s[k]*w3[k*4 + c];
    #pragma unroll
    for (int o = 16; o; o >>= 1) acc += __shfl_xor_sync(0xffffffffu, acc, o);
    if (l == 0) out[b*4 + c] = tanhf(acc + b3[c]);   // MAX_ACTION = 1.0
}

// ---------------- launch ----------------
extern "C" void kernel_launch(void* const* d_in, const int* in_sizes, int n_in,
                              void* d_out, int out_size) {
    const float* state     = (const float*)d_in[0];
    const float* Wheads    = (const float*)d_in[1];
    const float* a_src     = (const float*)d_in[2];
    const float* a_dst     = (const float*)d_in[3];
    const float* Wout      = (const float*)d_in[4];
    const float* a_out_src = (const float*)d_in[5];
    const float* a_out_dst = (const float*)d_in[6];
    const float* fc1_w     = (const float*)d_in[7];
    const float* fc1_b     = (const float*)d_in[8];
    const float* fc2_w     = (const float*)d_in[9];
    const float* fc2_b     = (const float*)d_in[10];
    const float* fc3_w     = (const float*)d_in[11];
    const float* fc3_b     = (const float*)d_in[12];
    float* out = (float*)d_out;

    const int attendSmem = (2048 + 512*64 + 2*17*64 + 64) * 4;   // 148224 B
    const int fc1Smem    = (32*512 + 512*16) * 4;                // 98304 B
    cudaFuncSetAttribute(k_attend, cudaFuncAttributeMaxDynamicSharedMemorySize, attendSmem);
    cudaFuncSetAttribute(k_fc1,    cudaFuncAttributeMaxDynamicSharedMemorySize, fc1Smem);

    // layer 1
    k_wh<<<2048, 256>>>(state, Wheads);
    k_scores<<<B_*H_, 512>>>(a_src, a_dst, 0, H_);
    k_attend<<<B_*H_, 512, attendSmem>>>(0, H_, H_*HID_, 1);
    // layer 2
    k_gemm2<<<256, 256>>>(Wout);
    k_scores<<<B_, 512>>>(a_out_src, a_out_dst, 1, 1);
    k_attend<<<B_, 512, attendSmem>>>(1, 1, OUT_, 0);
    // MLP head
    dim3 g5(16, 16);
    k_fc1<<<g5, 256, fc1Smem>>>(fc1_w);
    k_fc1red<<<B_, 256>>>(fc1_b);
    k_fc2<<<B_, 256>>>(fc2_w, fc2_b);
    k_fc3<<<B_, 128>>>(fc3_w, fc3_b, out);
}

// round 2
// speedup vs baseline: 1.1687x; 1.1687x over previous
#include <cuda_runtime.h>
#include <math.h>

#define B_    32
#define N_    512
#define F_    64
#define H_    8
#define HID_  64
#define OUT_  64

typedef unsigned long long ull;

// ---------------- scratch (device globals; no allocation) ----------------
__device__ float g_Wh  [B_*H_*N_*HID_];   // 33.5 MB
__device__ float g_ssrc[B_*H_*N_];
__device__ float g_sdst[B_*H_*N_];
__device__ float g_x   [B_*N_*H_*HID_];   // 33.5 MB
__device__ float g_Wh2 [B_*N_*OUT_];      // 4 MB
__device__ float g_s2s [B_*N_];
__device__ float g_s2d [B_*N_];
__device__ float g_z   [B_*N_*OUT_];      // 4 MB (fc1 input)
__device__ float g_p1  [64*B_*256];       // fc1 split-K partials
__device__ float g_z1  [B_*256];
__device__ float g_z2  [B_*256];

// ---------------- f32x2 packed-FMA helpers ----------------
__device__ __forceinline__ ull pk2(float x, float y) {
    ull r;
    asm("mov.b64 %0, {%1, %2};" : "=l"(r) : "r"(__float_as_uint(x)), "r"(__float_as_uint(y)));
    return r;
}
__device__ __forceinline__ float2 up2(ull v) {
    unsigned lo, hi;
    asm("mov.b64 {%0, %1}, %2;" : "=r"(lo), "=r"(hi) : "l"(v));
    return make_float2(__uint_as_float(lo), __uint_as_float(hi));
}
__device__ __forceinline__ void ffma2(ull& d, ull a, ull b) {
    asm("fma.rn.f32x2 %0, %1, %2, %0;" : "+l"(d) : "l"(a), "l"(b));
}

#define PITCH 68   // smem row pitch in floats (mult of 4 for .128 alignment)

// ---------------- K1: Wh = feat @ W_heads, fused s_src/s_dst scores --------
// grid 1024 = 32b x 8h x 4 rowtiles of 128; 128 threads; 8x8 per thread.
__global__ void k_wh(const float* __restrict__ state, const float* __restrict__ Wheads,
                     const float* __restrict__ a_src, const float* __restrict__ a_dst) {
    extern __shared__ float sm[];
    float* As = sm;                 // [128][PITCH]
    float* Ws = sm + 128*PITCH;     // [64][PITCH]
    int bt = blockIdx.x;
    int rt = bt & 3, h = (bt >> 2) & 7, b = bt >> 5;
    int rowbase = rt*128;
    int tid = threadIdx.x;
    int tx = tid & 7, ty = tid >> 3;      // tx: 8 col-groups, ty: 16 row-groups

    // stage A (128 rows x 64 cols of state) and W (64x64)
    {
        const float4* ap = (const float4*)(state + b*(N_*F_) + rowbase*F_);
        #pragma unroll
        for (int i = 0; i < 16; i++) {
            int idx = tid + i*128;        // 0..2047 float4
            int r = idx >> 4, k4 = idx & 15;
            *(float4*)(As + r*PITCH + 4*k4) = ap[idx];
        }
        const float4* wp = (const float4*)(Wheads + h*(F_*HID_));
        #pragma unroll
        for (int i = 0; i < 8; i++) {
            int idx = tid + i*128;        // 0..1023 float4
            int k = idx >> 4, c4 = idx & 15;
            *(float4*)(Ws + k*PITCH + 4*c4) = wp[idx];
        }
    }
    __syncthreads();

    ull acc[8][4] = {};
    #pragma unroll 8
    for (int k = 0; k < 64; k++) {
        ulonglong2 w0 = *(const ulonglong2*)(Ws + k*PITCH + tx*8);
        ulonglong2 w1 = *(const ulonglong2*)(Ws + k*PITCH + tx*8 + 4);
        #pragma unroll
        for (int i = 0; i < 8; i++) {
            float a = As[(ty + 16*i)*PITCH + k];
            ull ap = pk2(a, a);
            ffma2(acc[i][0], ap, w0.x);
            ffma2(acc[i][1], ap, w0.y);
            ffma2(acc[i][2], ap, w1.x);
            ffma2(acc[i][3], ap, w1.y);
        }
    }

    // epilogue: store Wh + fused attention scores
    int bh = b*H_ + h;
    float* op = g_Wh + ((size_t)bh*N_ + rowbase)*HID_;
    float as_[8], ad_[8];
    #pragma unroll
    for (int j = 0; j < 8; j++) { as_[j] = a_src[h*64 + tx*8 + j]; ad_[j] = a_dst[h*64 + tx*8 + j]; }
    #pragma unroll
    for (int i = 0; i < 8; i++) {
        int r = ty + 16*i;
        ulonglong2 v0; v0.x = acc[i][0]; v0.y = acc[i][1];
        ulonglong2 v1; v1.x = acc[i][2]; v1.y = acc[i][3];
        *(ulonglong2*)(op + r*64 + tx*8)     = v0;
        *(ulonglong2*)(op + r*64 + tx*8 + 4) = v1;
        float ps = 0.f, pd = 0.f;
        #pragma unroll
        for (int p = 0; p < 4; p++) {
            float2 u = up2(acc[i][p]);
            ps += u.x*as_[2*p] + u.y*as_[2*p+1];
            pd += u.x*ad_[2*p] + u.y*ad_[2*p+1];
        }
        #pragma unroll
        for (int o = 1; o < 8; o <<= 1) {
            ps += __shfl_xor_sync(0xffffffffu, ps, o);
            pd += __shfl_xor_sync(0xffffffffu, pd, o);
        }
        if (tx == 0) {
            g_ssrc[bh*N_ + rowbase + r] = ps;
            g_sdst[bh*N_ + rowbase + r] = pd;
        }
    }
}

// ---------------- K3: Wh2 = x @ W_out (16384x512 @ 512x64), fused scores ---
// grid 128 rowtiles of 128; 128 threads; 8x8 per thread; K-chunks of 64.
__global__ void k_gemm2(const float* __restrict__ Wout,
                        const float* __restrict__ a_out_src, const float* __restrict__ a_out_dst) {
    extern __shared__ float sm[];
    float* Xs = sm;                 // [128][PITCH]
    float* Ws = sm + 128*PITCH;     // [64][PITCH]
    int rt = blockIdx.x;
    int tid = threadIdx.x;
    int tx = tid & 7, ty = tid >> 3;
    const float4* xp = (const float4*)(g_x + (size_t)rt*128*512);

    ull acc[8][4] = {};
    for (int kc = 0; kc < 8; kc++) {
        __syncthreads();
        #pragma unroll
        for (int i = 0; i < 16; i++) {
            int idx = tid + i*128;
            int r = idx >> 4, k4 = idx & 15;
            *(float4*)(Xs + r*PITCH + 4*k4) = xp[r*128 + kc*16 + k4];
        }
        const float4* wp = (const float4*)(Wout + kc*64*64);
        #pragma unroll
        for (int i = 0; i < 8; i++) {
            int idx = tid + i*128;
            int k = idx >> 4, c4 = idx & 15;
            *(float4*)(Ws + k*PITCH + 4*c4) = wp[idx];
        }
        __syncthreads();
        #pragma unroll 8
        for (int k = 0; k < 64; k++) {
            ulonglong2 w0 = *(const ulonglong2*)(Ws + k*PITCH + tx*8);
            ulonglong2 w1 = *(const ulonglong2*)(Ws + k*PITCH + tx*8 + 4);
            #pragma unroll
            for (int i = 0; i < 8; i++) {
                float a = Xs[(ty + 16*i)*PITCH + k];
                ull ap = pk2(a, a);
                ffma2(acc[i][0], ap, w0.x);
                ffma2(acc[i][1], ap, w0.y);
                ffma2(acc[i][2], ap, w1.x);
                ffma2(acc[i][3], ap, w1.y);
            }
        }
    }

    // epilogue: store Wh2 + fused layer-2 scores
    int b  = (rt*128) >> 9;
    int n0 = (rt*128) & 511;
    float* op = g_Wh2 + (size_t)rt*128*64;
    float as_[8], ad_[8];
    #pragma unroll
    for (int j = 0; j < 8; j++) { as_[j] = a_out_src[tx*8 + j]; ad_[j] = a_out_dst[tx*8 + j]; }
    #pragma unroll
    for (int i = 0; i < 8; i++) {
        int r = ty + 16*i;
        ulonglong2 v0; v0.x = acc[i][0]; v0.y = acc[i][1];
        ulonglong2 v1; v1.x = acc[i][2]; v1.y = acc[i][3];
        *(ulonglong2*)(op + r*64 + tx*8)     = v0;
        *(ulonglong2*)(op + r*64 + tx*8 + 4) = v1;
        float ps = 0.f, pd = 0.f;
        #pragma unroll
        for (int p = 0; p < 4; p++) {
            float2 u = up2(acc[i][p]);
            ps += u.x*as_[2*p] + u.y*as_[2*p+1];
            pd += u.x*ad_[2*p] + u.y*ad_[2*p+1];
        }
        #pragma unroll
        for (int o = 1; o < 8; o <<= 1) {
            ps += __shfl_xor_sync(0xffffffffu, ps, o);
            pd += __shfl_xor_sync(0xffffffffu, pd, o);
        }
        if (tx == 0) {
            g_s2s[b*N_ + n0 + r] = ps;
            g_s2d[b*N_ + n0 + r] = pd;
        }
    }
}

// ---------------- K2/K4: sorted-prefix GAT attention (unchanged, correct) --
__global__ void k_attend(int layer, int heads, int rowStride, int applyElu) {
    extern __shared__ float sm[];
    float* ds   = sm;                    // 512
    int*   ji   = (int*)(sm + 512);      // 512
    float* Ed   = sm + 1024;             // 512
    float* Ed2  = sm + 1536;             // 512
    float* WhS  = sm + 2048;             // 512*64
    float* CP1  = WhS  + 512*64;         // 17*64
    float* CP2  = CP1  + 17*64;          // 17*64
    float* CPd1 = CP2  + 17*64;          // 32
    float* CPd2 = CPd1 + 32;             // 32

    const float* Wh   = layer ? g_Wh2 : g_Wh;
    const float* ssrc = layer ? g_s2s : g_ssrc;
    const float* sdst = layer ? g_s2d : g_sdst;
    float*       out  = layer ? g_z   : g_x;

    int bh = blockIdx.x;
    int hoff = (bh % heads)*64;
    const float* whbase = Wh + (size_t)bh*N_*64;
    int tid = threadIdx.x;

    ds[tid] = sdst[bh*N_ + tid];
    ji[tid] = tid;

    for (int k2 = 2; k2 <= 512; k2 <<= 1)
        for (int j = k2 >> 1; j > 0; j >>= 1) {
            __syncthreads();
            int i = tid, x = tid ^ j;
            if (x > i) {
                float a = ds[i], b = ds[x];
                bool desc = ((i & k2) == 0);
                if (desc ? (a < b) : (a > b)) {
                    ds[i] = b; ds[x] = a;
                    int t = ji[i]; ji[i] = ji[x]; ji[x] = t;
                }
            }
        }
    __syncthreads();
    float dmax = ds[0];
    {
        float dv = ds[tid] - dmax;
        Ed [tid] = expf(dv);
        Ed2[tid] = expf(0.2f*dv);
    }
    int w = tid >> 5, l = tid & 31;
    for (int u = w; u < 512; u += 16) {
        int jj = ji[u];
        float2 v = ((const float2*)(whbase + jj*64))[l];
        ((float2*)(WhS + u*64))[l] = v;
    }
    __syncthreads();
    for (int q = tid; q < 1024; q += 512) {
        int c = q >> 6, o = q & 63;
        float s1 = 0.f, s2 = 0.f;
        int ub = c*32;
        #pragma unroll 4
        for (int u = 0; u < 32; u++) {
            float wv = WhS[(ub + u)*64 + o];
            s1 += Ed [ub + u]*wv;
            s2 += Ed2[ub + u]*wv;
        }
        CP1[(c+1)*64 + o] = s1;
        CP2[(c+1)*64 + o] = s2;
    }
    if (tid < 64) { CP1[tid] = 0.f; CP2[tid] = 0.f; }
    if (tid < 16) {
        int c = tid; float s1 = 0.f, s2 = 0.f;
        for (int u = c*32; u < c*32 + 32; u++) { s1 += Ed[u]; s2 += Ed2[u]; }
        CPd1[c+1] = s1; CPd2[c+1] = s2;
    }
    if (tid == 0) { CPd1[0] = 0.f; CPd2[0] = 0.f; }
    __syncthreads();
    if (tid < 64) {
        for (int c = 1; c <= 16; c++) CP1[c*64 + tid] += CP1[(c-1)*64 + tid];
    } else if (tid < 128) {
        int o = tid - 64;
        for (int c = 1; c <= 16; c++) CP2[c*64 + o] += CP2[(c-1)*64 + o];
    } else if (tid == 128) {
        for (int c = 1; c <= 16; c++) { CPd1[c] += CPd1[c-1]; CPd2[c] += CPd2[c-1]; }
    }
    __syncthreads();

    float Td2 = CPd2[16];
    int bb = bh / heads;
    for (int r = w; r < 512; r += 16) {
        float s   = ssrc[bh*N_ + r];
        float sd0 = s + dmax;
        float m   = sd0 > 0.f ? sd0 : 0.2f*sd0;
        float A   = expf(sd0 - m);
        float Bv  = expf(0.2f*sd0 - m);
        float thr = -s;
        int lo = 0, hi = 512;
        #pragma unroll
        for (int it = 0; it < 9; it++) {
            int mid = (lo + hi) >> 1;
            if (ds[mid] > thr) lo = mid + 1; else hi = mid;
        }
        int k = lo;
        int c = k >> 5;
        float a1x = 0.f, a1y = 0.f, a2x = 0.f, a2y = 0.f, pe1 = 0.f, pe2 = 0.f;
        for (int u = c*32; u < k; u++) {
            float e1 = Ed[u], e2 = Ed2[u];
            float2 wv = ((const float2*)(WhS + u*64))[l];
            a1x += e1*wv.x; a1y += e1*wv.y;
            a2x += e2*wv.x; a2y += e2*wv.y;
            pe1 += e1;      pe2 += e2;
        }
        float2 cp1 = ((const float2*)(CP1 + c*64))[l];
        float2 cp2 = ((const float2*)(CP2 + c*64))[l];
        float2 t2  = ((const float2*)(CP2 + 16*64))[l];
        float posx = cp1.x + a1x, posy = cp1.y + a1y;
        float negx = t2.x - cp2.x - a2x, negy = t2.y - cp2.y - a2y;
        float den  = A*(CPd1[c] + pe1) + Bv*(Td2 - CPd2[c] - pe2);
        float inv  = 1.f/den;
        float o0 = (A*posx + Bv*negx)*inv;
        float o1 = (A*posy + Bv*negy)*inv;
        if (applyElu) {
            o0 = o0 > 0.f ? o0 : expm1f(o0);
            o1 = o1 > 0.f ? o1 : expm1f(o1);
        }
        ((float2*)(out + ((size_t)(bb*N_ + r))*rowStride + hoff))[l] = make_float2(o0, o1);
    }
}

// ---------------- K5: fc1 split-K  z(32,32768) @ w1(32768,256) -------------
// grid (4 colTiles of 64, 64 ksplits of 512); 128 threads; 4b x 4c / thread.
__global__ void k_fc1(const float* __restrict__ w1) {
    __shared__ float zS[32*PITCH];   // 32 x 64 per chunk
    __shared__ float wS[64*PITCH];   // 64 x 64 per chunk
    int ct = blockIdx.x, ksp = blockIdx.y;
    int tid = threadIdx.x;
    int tx = tid & 15, ty = tid >> 4;    // tx: 16 col-quads, ty: 8 batch-quads
    ull acc[4][2] = {};
    for (int ch = 0; ch < 8; ch++) {
        int k0 = ksp*512 + ch*64;
        __syncthreads();
        const float4* zg = (const float4*)g_z;
        #pragma unroll
        for (int i = 0; i < 4; i++) {
            int idx = tid + i*128;        // 0..511 float4
            int bb = idx >> 4, k4 = idx & 15;
            *(float4*)(zS + bb*PITCH + 4*k4) = zg[bb*8192 + (k0 >> 2) + k4];
        }
        const float4* wg = (const float4*)w1;
        #pragma unroll
        for (int i = 0; i < 8; i++) {
            int idx = tid + i*128;        // 0..1023 float4
            int kk = idx >> 4, c4 = idx & 15;
            *(float4*)(wS + kk*PITCH + 4*c4) = wg[(size_t)(k0 + kk)*64 + ct*16 + c4];
        }
        __syncthreads();
        #pragma unroll 8
        for (int kk = 0; kk < 64; kk++) {
            ulonglong2 wv = *(const ulonglong2*)(wS + kk*PITCH + tx*4);
            #pragma unroll
            for (int bb = 0; bb < 4; bb++) {
                float z = zS[(ty*4 + bb)*PITCH + kk];
                ull zp = pk2(z, z);
                ffma2(acc[bb][0], zp, wv.x);
                ffma2(acc[bb][1], zp, wv.y);
            }
        }
    }
    #pragma unroll
    for (int bb = 0; bb < 4; bb++) {
        float* pp = g_p1 + ((size_t)ksp*32 + ty*4 + bb)*256 + ct*64 + tx*4;
        ((ull*)pp)[0] = acc[bb][0];
        ((ull*)pp)[1] = acc[bb][1];
    }
}

// ---------------- K6: reduce split-K + bias + relu -------------------------
__global__ void k_fc1red(const float* __restrict__ b1) {
    int b = blockIdx.x, c = threadIdx.x;
    float acc = b1[c];
    #pragma unroll 8
    for (int ks = 0; ks < 64; ks++) acc += g_p1[((size_t)ks*32 + b)*256 + c];
    g_z1[b*256 + c] = fmaxf(acc, 0.f);
}

// ---------------- K7: fc2 + relu ----
__global__ void k_fc2(const float* __restrict__ w2, const float* __restrict__ b2) {
    __shared__ float z1s[256];
    int b = blockIdx.x, c = threadIdx.x;
    z1s[c] = g_z1[b*256 + c];
    __syncthreads();
    float acc = b2[c];
    #pragma unroll 8
    for (int k = 0; k < 256; k++) acc += z1s[k]*w2[k*256 + c];
    g_z2[b*256 + c] = fmaxf(acc, 0.f);
}

// ---------------- K8: fc3 + tanh ----
__global__ void k_fc3(const float* __restrict__ w3, const float* __restrict__ b3,
                      float* __restrict__ out) {
    __shared__ float z2s[256];
    int b = blockIdx.x, tid = threadIdx.x;
    z2s[tid] = g_z2[b*256 + tid];
    z2s[tid + 128] = g_z2[b*256 + tid + 128];
    __syncthreads();
    int c = tid >> 5, l = tid & 31;
    float acc = 0.f;
    #pragma unroll
    for (int k = l; k < 256; k += 32) acc += z2s[k]*w3[k*4 + c];
    #pragma unroll
    for (int o = 16; o; o >>= 1) acc += __shfl_xor_sync(0xffffffffu, acc, o);
    if (l == 0) out[b*4 + c] = tanhf(acc + b3[c]);   // MAX_ACTION = 1.0
}

// ---------------- launch ----------------
extern "C" void kernel_launch(void* const* d_in, const int* in_sizes, int n_in,
                              void* d_out, int out_size) {
    const float* state     = (const float*)d_in[0];
    const float* Wheads    = (const float*)d_in[1];
    const float* a_src     = (const float*)d_in[2];
    const float* a_dst     = (const float*)d_in[3];
    const float* Wout      = (const float*)d_in[4];
    const float* a_out_src = (const float*)d_in[5];
    const float* a_out_dst = (const float*)d_in[6];
    const float* fc1_w     = (const float*)d_in[7];
    const float* fc1_b     = (const float*)d_in[8];
    const float* fc2_w     = (const float*)d_in[9];
    const float* fc2_b     = (const float*)d_in[10];
    const float* fc3_w     = (const float*)d_in[11];
    const float* fc3_b     = (const float*)d_in[12];
    float* out = (float*)d_out;

    const int gemmSmem   = (128*PITCH + 64*PITCH) * 4;           // 52224 B
    const int attendSmem = (2048 + 512*64 + 2*17*64 + 64) * 4;   // 148224 B
    cudaFuncSetAttribute(k_wh,     cudaFuncAttributeMaxDynamicSharedMemorySize, gemmSmem);
    cudaFuncSetAttribute(k_gemm2,  cudaFuncAttributeMaxDynamicSharedMemorySize, gemmSmem);
    cudaFuncSetAttribute(k_attend, cudaFuncAttributeMaxDynamicSharedMemorySize, attendSmem);

    // layer 1 (scores fused into GEMM epilogue)
    k_wh<<<1024, 128, gemmSmem>>>(state, Wheads, a_src, a_dst);
    k_attend<<<B_*H_, 512, attendSmem>>>(0, H_, H_*HID_, 1);
    // layer 2
    k_gemm2<<<128, 128, gemmSmem>>>(Wout, a_out_src, a_out_dst);
    k_attend<<<B_, 512, attendSmem>>>(1, 1, OUT_, 0);
    // MLP head
    dim3 g5(4, 64);
    k_fc1<<<g5, 128>>>(fc1_w);
    k_fc1red<<<B_, 256>>>(fc1_b);
    k_fc2<<<B_, 256>>>(fc2_w, fc2_b);
    k_fc3<<<B_, 128>>>(fc3_w, fc3_b, out);
}

// round 3
// speedup vs baseline: 1.6447x; 1.4073x over previous
#include <cuda_runtime.h>
#include <math.h>

#define B_    32
#define N_    512
#define H_    8

typedef unsigned long long ull;

// ---------------- scratch (device globals; no allocation) ----------------
__device__ float g_x   [B_*N_*H_*64];     // 33.5 MB  post-attn layer1 (transposed)
__device__ float g_Wh2 [B_*N_*64];        // 4 MB
__device__ float g_s2s [B_*N_];
__device__ float g_s2d [B_*N_];
__device__ float g_z   [B_*N_*64];        // 4 MB (fc1 input)
__device__ float g_p1  [64*B_*256];
__device__ float g_z1  [B_*256];
__device__ float g_z2  [B_*256];

// ---------------- f32x2 packed-FMA helpers ----------------
__device__ __forceinline__ ull pk2(float x, float y) {
    ull r;
    asm("mov.b64 %0, {%1, %2};" : "=l"(r) : "r"(__float_as_uint(x)), "r"(__float_as_uint(y)));
    return r;
}
__device__ __forceinline__ float2 up2(ull v) {
    unsigned lo, hi;
    asm("mov.b64 {%0, %1}, %2;" : "=r"(lo), "=r"(hi) : "l"(v));
    return make_float2(__uint_as_float(lo), __uint_as_float(hi));
}
__device__ __forceinline__ void ffma2(ull& d, ull a, ull b) {
    asm("fma.rn.f32x2 %0, %1, %2, %0;" : "+l"(d) : "l"(a), "l"(b));
}

#define PITCH 68   // generic smem pitch (gemm2/fc1)
#define WHP   68   // Wh smem pitch
#define ASP   20   // A-chunk pitch
#define CPW   66   // prefix-table pitch (65 cols: 64 data + denominator)

// ============== shared attend phase ==============
// Wh[512][WHP] in smem (original row order), sS/dS = per-row src/dst scores.
// Sorts dst scores descending, builds chunk-8 two-branch prefix tables,
// then evaluates rows [r0, r1).
__device__ __forceinline__ void attend_phase(
    float* __restrict__ Wh, float* sS, float* dS, float* ds,
    float* Ed, float* Ed2, int* ji, ull* skey, float* CP1, float* CP2,
    int tid, int r0, int r1, float* outBase, int rowStride, int applyElu)
{
    __syncthreads();
    // ---- hybrid bitonic sort, descending by dS (u64 keys: mapped d | idx) --
    unsigned u0 = __float_as_uint(dS[tid]);
    u0 = (u0 & 0x80000000u) ? ~u0 : (u0 | 0x80000000u);   // order-preserving map
    ull v = ((ull)u0 << 32) | (unsigned)tid;
    for (int k2 = 2; k2 <= 512; k2 <<= 1) {
        for (int j = k2 >> 1; j; j >>= 1) {
            ull p;
            if (j >= 32) {
                __syncthreads();
                skey[tid] = v;
                __syncthreads();
                p = skey[tid ^ j];
            } else {
                p = __shfl_xor_sync(0xffffffffu, v, j);
            }
            bool keepBig = (((tid & j) == 0) == ((tid & k2) == 0));
            if (keepBig ? (p > v) : (p < v)) v = p;
        }
    }
    __syncthreads();
    int myj = (int)(unsigned)(v & 0xFFFFFFFFu);
    ji[tid] = myj;
    float dv_own = dS[myj];
    ds[tid] = dv_own;
    __syncthreads();
    float dmax = ds[0];
    float dd = dv_own - dmax;
    Ed[tid]  = expf(dd);
    Ed2[tid] = expf(0.2f*dd);
    __syncthreads();
    // ---- chunk sums (chunk = 8); col 64 is the denominator column ----
    for (int idx = tid; idx < 64*65; idx += 512) {
        int c = idx / 65, o = idx - c*65;
        float s1 = 0.f, s2 = 0.f;
        #pragma unroll
        for (int uu = 0; uu < 8; uu++) {
            int su = c*8 + uu;
            float e1 = Ed[su], e2 = Ed2[su];
            float wv = (o < 64) ? Wh[ji[su]*WHP + o] : 1.0f;
            s1 += e1*wv; s2 += e2*wv;
        }
        CP1[(c+1)*CPW + o] = s1;
        CP2[(c+1)*CPW + o] = s2;
    }
    if (tid < CPW) { CP1[tid] = 0.f; CP2[tid] = 0.f; }
    __syncthreads();
    // ---- Hillis-Steele inclusive scan over the 64 chunk rows ----
    for (int off = 1; off <= 32; off <<= 1) {
        float t1[9], t2[9];
        int n = 0;
        for (int idx = tid; idx < 64*65; idx += 512, n++) {
            int pos = idx / 65 + 1, col = idx - (pos-1)*65;
            bool ok = pos > off;
            t1[n] = ok ? CP1[(pos-off)*CPW + col] : 0.f;
            t2[n] = ok ? CP2[(pos-off)*CPW + col] : 0.f;
        }
        __syncthreads();
        n = 0;
        for (int idx = tid; idx < 64*65; idx += 512, n++) {
            int pos = idx / 65 + 1, col = idx - (pos-1)*65;
            CP1[pos*CPW + col] += t1[n];
            CP2[pos*CPW + col] += t2[n];
        }
        __syncthreads();
    }
    // ---- per-row: binary search + prefix lookup + <=7-term correction ----
    int w = tid >> 5, l = tid & 31;
    float2 T2v  = *(const float2*)(CP2 + 64*CPW + 2*l);
    float  T2d  = CP2[64*CPW + 64];
    for (int r = r0 + w; r < r1; r += 16) {
        float s   = sS[r];
        float sd0 = s + dmax;
        float m   = fmaxf(sd0, 0.2f*sd0);
        float A   = expf(sd0 - m);
        float Bv  = expf(0.2f*sd0 - m);
        float thr = -s;
        int lo = 0, hi = 512;
        #pragma unroll
        for (int it = 0; it < 9; it++) {
            int mid = (lo + hi) >> 1;
            if (ds[mid] > thr) lo = mid + 1; else hi = mid;
        }
        int k = lo, c = k >> 3;
        float a1x=0.f, a1y=0.f, a2x=0.f, a2y=0.f, pe1=0.f, pe2=0.f;
        for (int u2 = c*8; u2 < k; u2++) {
            float e1 = Ed[u2], e2 = Ed2[u2];
            float2 wv = *(const float2*)(Wh + ji[u2]*WHP + 2*l);
            a1x += e1*wv.x; a1y += e1*wv.y;
            a2x += e2*wv.x; a2y += e2*wv.y;
            pe1 += e1;      pe2 += e2;
        }
        float2 p1 = *(const float2*)(CP1 + c*CPW + 2*l);
        float2 p2 = *(const float2*)(CP2 + c*CPW + 2*l);
        float d1 = CP1[c*CPW + 64] + pe1;
        float d2 = T2d - CP2[c*CPW + 64] - pe2;
        float inv = 1.f / (A*d1 + Bv*d2);
        float o0 = (A*(p1.x + a1x) + Bv*(T2v.x - p2.x - a2x))*inv;
        float o1 = (A*(p1.y + a1y) + Bv*(T2v.y - p2.y - a2y))*inv;
        if (applyElu) {
            o0 = o0 > 0.f ? o0 : expm1f(o0);
            o1 = o1 > 0.f ? o1 : expm1f(o1);
        }
        *(float2*)(outBase + (size_t)r*rowStride + 2*l) = make_float2(o0, o1);
    }
}

// ============== fused layer-1: GEMM(512x64x64) + scores + attend ==========
// grid 256 = (b,h); 512 threads; smem 209920 B.
__global__ __launch_bounds__(512) void k_fused1(
    const float* __restrict__ state, const float* __restrict__ Wheads,
    const float* __restrict__ a_src, const float* __restrict__ a_dst)
{
    extern __shared__ float sm[];
    float* Wh     = sm;                    // 512*68 = 34816
    float* Ws     = sm + 34816;            // 64*68  = 4352
    float* region = sm + 39168;            // 10240  (As | skey | CP1+CP2)
    float* As     = region;
    ull*   skey   = (ull*)region;
    float* CP1    = region;
    float* CP2    = region + 65*CPW;       // 4290
    float* sS     = sm + 49408;
    float* dS     = sS + 512;
    float* ds     = dS + 512;
    float* Ed     = ds + 512;
    float* Ed2    = Ed + 512;
    int*   ji     = (int*)(Ed2 + 512);

    int bid = blockIdx.x;
    int b = bid >> 3, h = bid & 7;
    int tid = threadIdx.x;
    int tx = tid & 7, ty = tid >> 3;       // tx: 8 col-octets, ty: 64 row-groups

    // stage W[64][64]
    {
        const float4* wp = (const float4*)(Wheads + h*64*64);
        #pragma unroll
        for (int i = 0; i < 2; i++) {
            int idx = tid + i*512;
            int r = idx >> 4, c4 = idx & 15;
            *(float4*)(Ws + r*WHP + c4*4) = wp[idx];
        }
    }
    ull acc[8][4] = {};
    const float4* sp = (const float4*)(state + (size_t)b*N_*64);
    for (int kc = 0; kc < 4; kc++) {       // K chunks of 16
        __syncthreads();
        #pragma unroll
        for (int i = 0; i < 4; i++) {
            int idx = tid + i*512;         // 2048 float4
            int r = idx >> 2, q = idx & 3;
            *(float4*)(As + r*ASP + q*4) = sp[r*16 + kc*4 + q];
        }
        __syncthreads();
        #pragma unroll
        for (int k = 0; k < 16; k++) {
            ulonglong2 w0 = *(const ulonglong2*)(Ws + (kc*16+k)*WHP + tx*8);
            ulonglong2 w1 = *(const ulonglong2*)(Ws + (kc*16+k)*WHP + tx*8 + 4);
            #pragma unroll
            for (int i = 0; i < 8; i++) {
                float a = As[(ty + 64*i)*ASP + k];
                ull ap = pk2(a, a);
                ffma2(acc[i][0], ap, w0.x);
                ffma2(acc[i][1], ap, w0.y);
                ffma2(acc[i][2], ap, w1.x);
                ffma2(acc[i][3], ap, w1.y);
            }
        }
    }
    // epilogue: Wh -> smem, fused scores
    float as_[8], ad_[8];
    #pragma unroll
    for (int j2 = 0; j2 < 8; j2++) {
        as_[j2] = a_src[h*64 + tx*8 + j2];
        ad_[j2] = a_dst[h*64 + tx*8 + j2];
    }
    #pragma unroll
    for (int i = 0; i < 8; i++) {
        int r = ty + 64*i;
        *(ulonglong2*)(Wh + r*WHP + tx*8)     = make_ulonglong2(acc[i][0], acc[i][1]);
        *(ulonglong2*)(Wh + r*WHP + tx*8 + 4) = make_ulonglong2(acc[i][2], acc[i][3]);
        float ps = 0.f, pd = 0.f;
        #pragma unroll
        for (int p = 0; p < 4; p++) {
            float2 uu = up2(acc[i][p]);
            ps += uu.x*as_[2*p] + uu.y*as_[2*p+1];
            pd += uu.x*ad_[2*p] + uu.y*ad_[2*p+1];
        }
        #pragma unroll
        for (int o = 1; o < 8; o <<= 1) {
            ps += __shfl_xor_sync(0xffffffffu, ps, o);
            pd += __shfl_xor_sync(0xffffffffu, pd, o);
        }
        if (tx == 0) { sS[r] = ps; dS[r] = pd; }
    }
    attend_phase(Wh, sS, dS, ds, Ed, Ed2, ji, skey, CP1, CP2, tid,
                 0, 512, g_x + (size_t)b*N_*512 + h*64, 512, 1);
}

// ============== K3: Wh2 = x @ W_out (16384x512 @ 512x64) + fused scores ===
__global__ void k_gemm2(const float* __restrict__ Wout,
                        const float* __restrict__ a_out_src, const float* __restrict__ a_out_dst) {
    extern __shared__ float sm[];
    float* Xs = sm;                 // [128][PITCH]
    float* Ws = sm + 128*PITCH;     // [64][PITCH]
    int rt = blockIdx.x;
    int tid = threadIdx.x;
    int tx = tid & 7, ty = tid >> 3;
    const float4* xp = (const float4*)(g_x + (size_t)rt*128*512);

    ull acc[8][4] = {};
    for (int kc = 0; kc < 8; kc++) {
        __syncthreads();
        #pragma unroll
        for (int i = 0; i < 16; i++) {
            int idx = tid + i*128;
            int r = idx >> 4, k4 = idx & 15;
            *(float4*)(Xs + r*PITCH + 4*k4) = xp[r*128 + kc*16 + k4];
        }
        const float4* wp = (const float4*)(Wout + kc*64*64);
        #pragma unroll
        for (int i = 0; i < 8; i++) {
            int idx = tid + i*128;
            int k = idx >> 4, c4 = idx & 15;
            *(float4*)(Ws + k*PITCH + 4*c4) = wp[idx];
        }
        __syncthreads();
        #pragma unroll 8
        for (int k = 0; k < 64; k++) {
            ulonglong2 w0 = *(const ulonglong2*)(Ws + k*PITCH + tx*8);
            ulonglong2 w1 = *(const ulonglong2*)(Ws + k*PITCH + tx*8 + 4);
            #pragma unroll
            for (int i = 0; i < 8; i++) {
                float a = Xs[(ty + 16*i)*PITCH + k];
                ull ap = pk2(a, a);
                ffma2(acc[i][0], ap, w0.x);
                ffma2(acc[i][1], ap, w0.y);
                ffma2(acc[i][2], ap, w1.x);
                ffma2(acc[i][3], ap, w1.y);
            }
        }
    }
    int b  = (rt*128) >> 9;
    int n0 = (rt*128) & 511;
    float* op = g_Wh2 + (size_t)rt*128*64;
    float as_[8], ad_[8];
    #pragma unroll
    for (int j = 0; j < 8; j++) { as_[j] = a_out_src[tx*8 + j]; ad_[j] = a_out_dst[tx*8 + j]; }
    #pragma unroll
    for (int i = 0; i < 8; i++) {
        int r = ty + 16*i;
        ulonglong2 v0; v0.x = acc[i][0]; v0.y = acc[i][1];
        ulonglong2 v1; v1.x = acc[i][2]; v1.y = acc[i][3];
        *(ulonglong2*)(op + r*64 + tx*8)     = v0;
        *(ulonglong2*)(op + r*64 + tx*8 + 4) = v1;
        float ps = 0.f, pd = 0.f;
        #pragma unroll
        for (int p = 0; p < 4; p++) {
            float2 u = up2(acc[i][p]);
            ps += u.x*as_[2*p] + u.y*as_[2*p+1];
            pd += u.x*ad_[2*p] + u.y*ad_[2*p+1];
        }
        #pragma unroll
        for (int o = 1; o < 8; o <<= 1) {
            ps += __shfl_xor_sync(0xffffffffu, ps, o);
            pd += __shfl_xor_sync(0xffffffffu, pd, o);
        }
        if (tx == 0) {
            g_s2s[b*N_ + n0 + r] = ps;
            g_s2d[b*N_ + n0 + r] = pd;
        }
    }
}

// ============== K4: layer-2 attend, 4-way row split ==============
// grid 128 = (b, quarter); 512 threads; smem 185872 B.
__global__ __launch_bounds__(512) void k_attend2() {
    extern __shared__ float sm[];
    float* Wh     = sm;                    // 34816
    float* region = sm + 34816;            // 8580 (skey | CP1+CP2)
    ull*   skey   = (ull*)region;
    float* CP1    = region;
    float* CP2    = region + 65*CPW;
    float* sS     = sm + 43396;
    float* dS     = sS + 512;
    float* ds     = dS + 512;
    float* Ed     = ds + 512;
    float* Ed2    = Ed + 512;
    int*   ji     = (int*)(Ed2 + 512);

    int bid = blockIdx.x;
    int b = bid >> 2, q = bid & 3;
    int tid = threadIdx.x;
    const float4* src = (const float4*)(g_Wh2 + (size_t)b*N_*64);
    #pragma unroll
    for (int i = 0; i < 16; i++) {
        int idx = tid + i*512;
        int r = idx >> 4, c4 = idx & 15;
        *(float4*)(Wh + r*WHP + c4*4) = src[idx];
    }
    sS[tid] = g_s2s[b*N_ + tid];
    dS[tid] = g_s2d[b*N_ + tid];
    attend_phase(Wh, sS, dS, ds, Ed, Ed2, ji, skey, CP1, CP2, tid,
                 q*128, q*128 + 128, g_z + (size_t)b*N_*64, 64, 0);
}

// ============== fc head (unchanged) ==============
__global__ void k_fc1(const float* __restrict__ w1) {
    __shared__ float zS[32*PITCH];
    __shared__ float wS[64*PITCH];
    int ct = blockIdx.x, ksp = blockIdx.y;
    int tid = threadIdx.x;
    int tx = tid & 15, ty = tid >> 4;
    ull acc[4][2] = {};
    for (int ch = 0; ch < 8; ch++) {
        int k0 = ksp*512 + ch*64;
        __syncthreads();
        const float4* zg = (const float4*)g_z;
        #pragma unroll
        for (int i = 0; i < 4; i++) {
            int idx = tid + i*128;
            int bb = idx >> 4, k4 = idx & 15;
            *(float4*)(zS + bb*PITCH + 4*k4) = zg[bb*8192 + (k0 >> 2) + k4];
        }
        const float4* wg = (const float4*)w1;
        #pragma unroll
        for (int i = 0; i < 8; i++) {
            int idx = tid + i*128;
            int kk = idx >> 4, c4 = idx & 15;
            *(float4*)(wS + kk*PITCH + 4*c4) = wg[(size_t)(k0 + kk)*64 + ct*16 + c4];
        }
        __syncthreads();
        #pragma unroll 8
        for (int kk = 0; kk < 64; kk++) {
            ulonglong2 wv = *(const ulonglong2*)(wS + kk*PITCH + tx*4);
            #pragma unroll
            for (int bb = 0; bb < 4; bb++) {
                float z = zS[(ty*4 + bb)*PITCH + kk];
                ull zp = pk2(z, z);
                ffma2(acc[bb][0], zp, wv.x);
                ffma2(acc[bb][1], zp, wv.y);
            }
        }
    }
    #pragma unroll
    for (int bb = 0; bb < 4; bb++) {
        float* pp = g_p1 + ((size_t)ksp*32 + ty*4 + bb)*256 + ct*64 + tx*4;
        ((ull*)pp)[0] = acc[bb][0];
        ((ull*)pp)[1] = acc[bb][1];
    }
}

__global__ void k_fc1red(const float* __restrict__ b1) {
    int b = blockIdx.x, c = threadIdx.x;
    float acc = b1[c];
    #pragma unroll 8
    for (int ks = 0; ks < 64; ks++) acc += g_p1[((size_t)ks*32 + b)*256 + c];
    g_z1[b*256 + c] = fmaxf(acc, 0.f);
}

__global__ void k_fc2(const float* __restrict__ w2, const float* __restrict__ b2) {
    __shared__ float z1s[256];
    int b = blockIdx.x, c = threadIdx.x;
    z1s[c] = g_z1[b*256 + c];
    __syncthreads();
    float acc = b2[c];
    #pragma unroll 8
    for (int k = 0; k < 256; k++) acc += z1s[k]*w2[k*256 + c];
    g_z2[b*256 + c] = fmaxf(acc, 0.f);
}

__global__ void k_fc3(const float* __restrict__ w3, const float* __restrict__ b3,
                      float* __restrict__ out) {
    __shared__ float z2s[256];
    int b = blockIdx.x, tid = threadIdx.x;
    z2s[tid] = g_z2[b*256 + tid];
    z2s[tid + 128] = g_z2[b*256 + tid + 128];
    __syncthreads();
    int c = tid >> 5, l = tid & 31;
    float acc = 0.f;
    #pragma unroll
    for (int k = l; k < 256; k += 32) acc += z2s[k]*w3[k*4 + c];
    #pragma unroll
    for (int o = 16; o; o >>= 1) acc += __shfl_xor_sync(0xffffffffu, acc, o);
    if (l == 0) out[b*4 + c] = tanhf(acc + b3[c]);
}

// ---------------- launch ----------------
extern "C" void kernel_launch(void* const* d_in, const int* in_sizes, int n_in,
                              void* d_out, int out_size) {
    const float* state     = (const float*)d_in[0];
    const float* Wheads    = (const float*)d_in[1];
    const float* a_src     = (const float*)d_in[2];
    const float* a_dst     = (const float*)d_in[3];
    const float* Wout      = (const float*)d_in[4];
    const float* a_out_src = (const float*)d_in[5];
    const float* a_out_dst = (const float*)d_in[6];
    const float* fc1_w     = (const float*)d_in[7];
    const float* fc1_b     = (const float*)d_in[8];
    const float* fc2_w     = (const float*)d_in[9];
    const float* fc2_b     = (const float*)d_in[10];
    const float* fc3_w     = (const float*)d_in[11];
    const float* fc3_b     = (const float*)d_in[12];
    float* out = (float*)d_out;

    const int fusedSmem   = 52480 * 4;                 // 209920 B
    const int attend2Smem = 46468 * 4;                 // 185872 B
    const int gemmSmem    = (128*PITCH + 64*PITCH)*4;  // 52224 B
    cudaFuncSetAttribute(k_fused1,  cudaFuncAttributeMaxDynamicSharedMemorySize, fusedSmem);
    cudaFuncSetAttribute(k_attend2, cudaFuncAttributeMaxDynamicSharedMemorySize, attend2Smem);
    cudaFuncSetAttribute(k_gemm2,   cudaFuncAttributeMaxDynamicSharedMemorySize, gemmSmem);

    // layer 1: fully fused per (b,h)
    k_fused1<<<256, 512, fusedSmem>>>(state, Wheads, a_src, a_dst);
    // layer 2
    k_gemm2<<<128, 128, gemmSmem>>>(Wout, a_out_src, a_out_dst);
    k_attend2<<<128, 512, attend2Smem>>>();
    // MLP head
    dim3 g5(4, 64);
    k_fc1<<<g5, 128>>>(fc1_w);
    k_fc1red<<<B_, 256>>>(fc1_b);
    k_fc2<<<B_, 256>>>(fc2_w, fc2_b);
    k_fc3<<<B_, 128>>>(fc3_w, fc3_b, out);
}